// round 13
// baseline (speedup 1.0000x reference)
#include <cuda_runtime.h>
#include <cuda_bf16.h>
#include <cstdint>

// Fixed problem maxima (from reference): 1M edges, 100K nodes, 2M pairs.
#define NE_MAX 1000000
#define NN_MAX 100000
#define NP_MAX 2000000
#define NWIN 4

__device__ float g_P[(size_t)NE_MAX * 64];   // edge_attr @ W_edge[:, :64]^T
__device__ float g_Q[(size_t)NN_MAX * 64];   // [x|gs]    @ W_edge[:, 64:]^T
__device__ int   g_cnt4[NWIN];               // records per window
__device__ int4  g_rec[(size_t)NWIN * NP_MAX]; // compacted {e0,e1,a0} per window

__device__ __forceinline__ float eluf(float x) {
    return x > 0.f ? x : (__expf(x) - 1.f);
}
__device__ __forceinline__ uint32_t smem_u32(const void* p) {
    uint32_t a;
    asm("{ .reg .u64 t; cvta.to.shared.u64 t, %1; cvt.u32.u64 %0, t; }" : "=r"(a) : "l"(p));
    return a;
}
// pack two floats to bf16x2 (first arg -> low 16 bits)
__device__ __forceinline__ uint32_t pack_bf(float lo, float hi) {
    uint32_t r; asm("cvt.rn.bf16x2.f32 %0, %1, %2;" : "=r"(r) : "f"(hi), "f"(lo)); return r;
}
// residual (lo-part) of a float2 vs its packed bf16 hi
__device__ __forceinline__ uint32_t resid_bf(float a, float b, uint32_t h) {
    return pack_bf(a - __uint_as_float(h << 16), b - __uint_as_float(h & 0xFFFF0000u));
}
__device__ __forceinline__ void ldm_x4(uint32_t* r, uint32_t addr) {
    asm volatile("ldmatrix.sync.aligned.m8n8.x4.shared.b16 {%0,%1,%2,%3}, [%4];"
                 : "=r"(r[0]), "=r"(r[1]), "=r"(r[2]), "=r"(r[3]) : "r"(addr));
}
__device__ __forceinline__ void mma_bf16(float* d, const uint32_t* a, uint32_t b0, uint32_t b1) {
    asm volatile(
        "mma.sync.aligned.m16n8k16.row.col.f32.bf16.bf16.f32 "
        "{%0,%1,%2,%3}, {%4,%5,%6,%7}, {%8,%9}, {%0,%1,%2,%3};"
        : "+f"(d[0]), "+f"(d[1]), "+f"(d[2]), "+f"(d[3])
        : "r"(a[0]), "r"(a[1]), "r"(a[2]), "r"(a[3]), "r"(b0), "r"(b1));
}
__device__ __forceinline__ void split_store(char* dhi, char* dlo, float4 v) {
    uint32_t h0 = pack_bf(v.x, v.y);
    uint32_t l0 = resid_bf(v.x, v.y, h0);
    uint32_t h1 = pack_bf(v.z, v.w);
    uint32_t l1 = resid_bf(v.z, v.w, h1);
    *(uint32_t*)(dhi)     = h0;
    *(uint32_t*)(dhi + 4) = h1;
    *(uint32_t*)(dlo)     = l0;
    *(uint32_t*)(dlo + 4) = l1;
}

// ---------------------------------------------------------------------------
// Fused K1+K2 (unchanged from round 12 — best measured).
// ---------------------------------------------------------------------------
#define ASTRIDE 144
#define SM_BHI  0
#define SM_BLO  18432
#define SM_BIAS 36864
#define SM_NW   37120
#define SM_XS   (SM_NW + 10752)
#define SM_TOT  (SM_XS + 22176)

__global__ __launch_bounds__(256) void fused_gemm_kernel(
    const float* __restrict__ E,
    const float* __restrict__ W_edge,
    const float* __restrict__ W_e,
    const float* __restrict__ b_e,
    const float* __restrict__ x,
    const float* __restrict__ gs,
    float* __restrict__ out,
    int NE, int NN) {
    extern __shared__ char sm[];
    uint32_t smb = smem_u32(sm);
    float* Wn = (float*)(sm + SM_NW);
    float* Xs = (float*)(sm + SM_XS);
    int tid  = threadIdx.x;
    int wid  = tid >> 5;
    int lane = tid & 31;

    if (tid < 64) *(float*)(sm + SM_BIAS + tid * 4) = b_e[tid];

    for (int s = tid; s < 128 * 16; s += 256) {
        int o = s >> 4, q = s & 15;
        float4 v;
        if (o < 64) {
            v = *(const float4*)&W_e[o * 64 + q * 4];
        } else {
            const float* wr = &W_edge[(o - 64) * 106 + q * 4];
            v = make_float4(wr[0], wr[1], wr[2], wr[3]);
        }
        split_store(sm + SM_BHI + o * ASTRIDE + q * 8,
                    sm + SM_BLO + o * ASTRIDE + q * 8, v);
    }
    for (int s = tid; s < 64 * 42; s += 256) {
        int o = s / 42, i = s % 42;
        Wn[i * 64 + o] = W_edge[o * 106 + 64 + i];
    }
    __syncthreads();

    int brow = lane & 7;
    int bk   = (lane >> 3) * 8;
    uint32_t boff = (uint32_t)(brow * ASTRIDE + bk * 2);
    int g  = lane >> 2;
    int tq = lane & 3;
    int cb = tq * 2;

    int ntiles_e = (NE + 127) >> 7;
    int ntiles_n = (NN + 127) >> 7;
    int nk = ntiles_n > (ntiles_e + 9) / 10 ? ntiles_n : (ntiles_e + 9) / 10;
    long long umax = 11LL * nk + 11;

    for (long long u = blockIdx.x; u < umax; u += gridDim.x) {
        int k11 = (int)(u / 11), r11 = (int)(u % 11);

        if (r11 == 10) {
            // ---------------- node tile (block-wide, synced) ----------------
            int tn = k11;
            if (tn >= ntiles_n) continue;
            int n0 = tn << 7;
            __syncthreads();
            for (int s = tid; s < 128 * 37; s += 256) {
                int nl = s / 37, i = s % 37;
                float v = (n0 + nl < NN) ? x[(size_t)n0 * 37 + s] : 0.f;
                Xs[i * 132 + nl] = v;
            }
            for (int s = tid; s < 128 * 5; s += 256) {
                int nl = s / 5, j = s % 5;
                float v = (n0 + nl < NN) ? gs[(size_t)n0 * 5 + s] : 0.f;
                Xs[(37 + j) * 132 + nl] = v;
            }
            __syncthreads();

            int tr = tid >> 3, tc = tid & 7;
            float acc[4][8];
#pragma unroll
            for (int r = 0; r < 4; r++)
#pragma unroll
                for (int c = 0; c < 8; c++) acc[r][c] = 0.f;

#pragma unroll 6
            for (int k = 0; k < 42; k++) {
                float a[4], w[8];
                *(float4*)a       = *(const float4*)&Xs[k * 132 + tr * 4];
                *(float4*)w       = *(const float4*)&Wn[k * 64 + tc * 8];
                *(float4*)(w + 4) = *(const float4*)&Wn[k * 64 + tc * 8 + 4];
#pragma unroll
                for (int r = 0; r < 4; r++)
#pragma unroll
                    for (int c = 0; c < 8; c++)
                        acc[r][c] = fmaf(a[r], w[c], acc[r][c]);
            }
#pragma unroll
            for (int r = 0; r < 4; r++) {
                int n = n0 + tr * 4 + r;
                if (n < NN) {
                    *(float4*)&g_Q[(size_t)n * 64 + tc * 8]     = *(float4*)&acc[r][0];
                    *(float4*)&g_Q[(size_t)n * 64 + tc * 8 + 4] = *(float4*)&acc[r][4];
                }
            }
        } else {
            // ---------------- edge tile (per-warp, barrier-free) ------------
            int te = k11 * 10 + r11;
            if (te >= ntiles_e) continue;
            int row0 = te << 7;

            int r0 = row0 + wid * 16 + g;
            int r1 = r0 + 8;
            uint32_t Ah[4][4], Al[4][4];
            const float2 z2 = make_float2(0.f, 0.f);
#pragma unroll
            for (int k = 0; k < 4; k++) {
                int c0 = k * 16 + cb;
                float2 v00 = z2, v01 = z2, v10 = z2, v11 = z2;
                if (r0 < NE) {
                    v00 = __ldg((const float2*)&E[(size_t)r0 * 64 + c0]);
                    v01 = __ldg((const float2*)&E[(size_t)r0 * 64 + c0 + 8]);
                }
                if (r1 < NE) {
                    v10 = __ldg((const float2*)&E[(size_t)r1 * 64 + c0]);
                    v11 = __ldg((const float2*)&E[(size_t)r1 * 64 + c0 + 8]);
                }
                Ah[k][0] = pack_bf(v00.x, v00.y);
                Ah[k][1] = pack_bf(v10.x, v10.y);
                Ah[k][2] = pack_bf(v01.x, v01.y);
                Ah[k][3] = pack_bf(v11.x, v11.y);
                Al[k][0] = resid_bf(v00.x, v00.y, Ah[k][0]);
                Al[k][1] = resid_bf(v10.x, v10.y, Ah[k][1]);
                Al[k][2] = resid_bf(v01.x, v01.y, Ah[k][2]);
                Al[k][3] = resid_bf(v11.x, v11.y, Ah[k][3]);
            }

#pragma unroll 2
            for (int j = 0; j < 16; j++) {
                uint32_t nb = (uint32_t)(j * 8 * ASTRIDE) + boff;
                uint32_t Bh[8], Bl[8];
                ldm_x4(Bh,     smb + SM_BHI + nb);
                ldm_x4(Bh + 4, smb + SM_BHI + nb + 64);
                ldm_x4(Bl,     smb + SM_BLO + nb);
                ldm_x4(Bl + 4, smb + SM_BLO + nb + 64);

                float acc[4] = {0.f, 0.f, 0.f, 0.f};
#pragma unroll
                for (int k = 0; k < 4; k++) {
                    mma_bf16(acc, Ah[k], Bh[k * 2], Bh[k * 2 + 1]);
                    mma_bf16(acc, Al[k], Bh[k * 2], Bh[k * 2 + 1]);
                    mma_bf16(acc, Ah[k], Bl[k * 2], Bl[k * 2 + 1]);
                }

                int ra = row0 + wid * 16 + g;
                int rb = ra + 8;
                int c  = j * 8 + tq * 2;
                if (j < 8) {
                    float2 bb = *(float2*)(sm + SM_BIAS + c * 4);
                    if (ra < NE) {
                        float2 v = make_float2(eluf(acc[0] + bb.x), eluf(acc[1] + bb.y));
                        *(float2*)&out[(size_t)ra * 64 + c] = v;
                    }
                    if (rb < NE) {
                        float2 v = make_float2(eluf(acc[2] + bb.x), eluf(acc[3] + bb.y));
                        *(float2*)&out[(size_t)rb * 64 + c] = v;
                    }
                } else {
                    int cp = c - 64;
                    if (ra < NE)
                        *(float2*)&g_P[(size_t)ra * 64 + cp] = make_float2(acc[0], acc[1]);
                    if (rb < NE)
                        *(float2*)&g_P[(size_t)rb * 64 + cp] = make_float2(acc[2], acc[3]);
                }
            }
        }
    }
}

// ---------------------------------------------------------------------------
// K3a: zero window counters.
// ---------------------------------------------------------------------------
__global__ void zero_cnt_kernel() {
    if (threadIdx.x < NWIN) g_cnt4[threadIdx.x] = 0;
}

// ---------------------------------------------------------------------------
// K3b: compact pair records into NWIN e0-window lists.
// smem-aggregated counters: NWIN global atomics per block total.
// ---------------------------------------------------------------------------
__global__ __launch_bounds__(256) void bucket_kernel(
    const int* __restrict__ aidx,
    const int* __restrict__ eidx,
    int NP, int NE) {
    __shared__ int scnt[NWIN];
    __shared__ int sbase[NWIN];
    int tid = threadIdx.x;
    if (tid < NWIN) scnt[tid] = 0;
    __syncthreads();

    long long k = (long long)blockIdx.x * 256 + tid;
    int w = 0, loc = 0, e0 = 0, e1 = 0, a0 = 0;
    bool valid = (k < NP);
    if (valid) {
        e0 = eidx[k];
        e1 = eidx[(size_t)NP + k];
        a0 = aidx[k];
        w = (int)(((long long)e0 * NWIN) / NE);
        if (w > NWIN - 1) w = NWIN - 1;
        loc = atomicAdd(&scnt[w], 1);
    }
    __syncthreads();
    if (tid < NWIN) sbase[tid] = atomicAdd(&g_cnt4[tid], scnt[tid]);
    __syncthreads();
    if (valid) {
        int pos = sbase[w] + loc;
        g_rec[(size_t)w * NP_MAX + pos] = make_int4(e0, e1, a0, 0);
    }
}

// ---------------------------------------------------------------------------
// K3c: GRID-STRIDE sweep of one window's compacted list. Persistent blocks,
// no dead blocks, no per-window launch ramp. Out window (NE/NWIN rows,
// 64 MB) stays L2-resident -> out lines fetched once + written back once.
// ---------------------------------------------------------------------------
__global__ __launch_bounds__(256) void pair_sweep_kernel(
    const float* __restrict__ b_edge,
    float* __restrict__ out,
    int win) {
    __shared__ float bs[64];
    int tid = threadIdx.x;
    if (tid < 64) bs[tid] = b_edge[tid];
    __syncthreads();

    int nrec = g_cnt4[win];
    int pl = tid >> 4;
    int q  = tid & 15;
    const int4* rec = g_rec + (size_t)win * NP_MAX;
    float4 b4 = *(float4*)&bs[q * 4];

    for (long long i = (long long)blockIdx.x * 16 + pl; i < nrec;
         i += (long long)gridDim.x * 16) {
        int4 r = __ldg(&rec[i]);
        int e0 = r.x, e1 = r.y, a0 = r.z;

        float4 p  = __ldg((const float4*)&g_P[(size_t)e1 * 64 + q * 4]);
        float4 qv = __ldg((const float4*)&g_Q[(size_t)a0 * 64 + q * 4]);

        float h0 = eluf(p.x + qv.x + b4.x);
        float h1 = eluf(p.y + qv.y + b4.y);
        float h2 = eluf(p.z + qv.z + b4.z);
        float h3 = eluf(p.w + qv.w + b4.w);

        float* addr = out + (size_t)e0 * 64 + q * 4;
        asm volatile("red.global.add.v4.f32 [%0], {%1,%2,%3,%4};"
                     :: "l"(addr), "f"(h0), "f"(h1), "f"(h2), "f"(h3)
                     : "memory");
    }
}

// ---------------------------------------------------------------------------
extern "C" void kernel_launch(void* const* d_in, const int* in_sizes, int n_in,
                              void* d_out, int out_size) {
    const float* x      = (const float*)d_in[0];
    const float* gs     = (const float*)d_in[1];
    const float* E      = (const float*)d_in[2];
    const float* W_edge = (const float*)d_in[3];
    const float* b_edge = (const float*)d_in[4];
    const float* W_e    = (const float*)d_in[5];
    const float* b_e    = (const float*)d_in[6];
    const int*   aidx   = (const int*)d_in[7];
    const int*   eidx   = (const int*)d_in[8];
    float* out = (float*)d_out;

    int NN = in_sizes[0] / 37;
    int NE = in_sizes[2] / 64;
    int NP = in_sizes[7] / 2;
    if (NN > NN_MAX) NN = NN_MAX;
    if (NE > NE_MAX) NE = NE_MAX;
    if (NP > NP_MAX) NP = NP_MAX;

    cudaFuncSetAttribute(fused_gemm_kernel,
                         cudaFuncAttributeMaxDynamicSharedMemorySize, SM_TOT);
    fused_gemm_kernel<<<296, 256, SM_TOT>>>(E, W_edge, W_e, b_e, x, gs, out, NE, NN);

    // K3: compact by e0 window, then persistent grid-stride sweeps.
    zero_cnt_kernel<<<1, 32>>>();
    bucket_kernel<<<(NP + 255) / 256, 256>>>(aidx, eidx, NP, NE);
    for (int w = 0; w < NWIN; w++)
        pair_sweep_kernel<<<1184, 256>>>(b_edge, out, w);
}

// round 14
// speedup vs baseline: 1.0451x; 1.0451x over previous
#include <cuda_runtime.h>
#include <cuda_bf16.h>
#include <cstdint>

// Fixed problem maxima (from reference): 1M edges, 100K nodes, 2M pairs.
#define NE_MAX 1000000
#define NN_MAX 100000

__device__ float g_P[(size_t)NE_MAX * 64];   // edge_attr @ W_edge[:, :64]^T
__device__ float g_Q[(size_t)NN_MAX * 64];   // [x|gs]    @ W_edge[:, 64:]^T

__device__ __forceinline__ float eluf(float x) {
    return x > 0.f ? x : (__expf(x) - 1.f);
}
__device__ __forceinline__ uint32_t smem_u32(const void* p) {
    uint32_t a;
    asm("{ .reg .u64 t; cvta.to.shared.u64 t, %1; cvt.u32.u64 %0, t; }" : "=r"(a) : "l"(p));
    return a;
}
// pack two floats to bf16x2 (first arg -> low 16 bits)
__device__ __forceinline__ uint32_t pack_bf(float lo, float hi) {
    uint32_t r; asm("cvt.rn.bf16x2.f32 %0, %1, %2;" : "=r"(r) : "f"(hi), "f"(lo)); return r;
}
// residual (lo-part) of a float2 vs its packed bf16 hi
__device__ __forceinline__ uint32_t resid_bf(float a, float b, uint32_t h) {
    return pack_bf(a - __uint_as_float(h << 16), b - __uint_as_float(h & 0xFFFF0000u));
}
__device__ __forceinline__ void ldm_x4(uint32_t* r, uint32_t addr) {
    asm volatile("ldmatrix.sync.aligned.m8n8.x4.shared.b16 {%0,%1,%2,%3}, [%4];"
                 : "=r"(r[0]), "=r"(r[1]), "=r"(r[2]), "=r"(r[3]) : "r"(addr));
}
__device__ __forceinline__ void mma_bf16(float* d, const uint32_t* a, uint32_t b0, uint32_t b1) {
    asm volatile(
        "mma.sync.aligned.m16n8k16.row.col.f32.bf16.bf16.f32 "
        "{%0,%1,%2,%3}, {%4,%5,%6,%7}, {%8,%9}, {%0,%1,%2,%3};"
        : "+f"(d[0]), "+f"(d[1]), "+f"(d[2]), "+f"(d[3])
        : "r"(a[0]), "r"(a[1]), "r"(a[2]), "r"(a[3]), "r"(b0), "r"(b1));
}
__device__ __forceinline__ void split_store(char* dhi, char* dlo, float4 v) {
    uint32_t h0 = pack_bf(v.x, v.y);
    uint32_t l0 = resid_bf(v.x, v.y, h0);
    uint32_t h1 = pack_bf(v.z, v.w);
    uint32_t l1 = resid_bf(v.z, v.w, h1);
    *(uint32_t*)(dhi)     = h0;
    *(uint32_t*)(dhi + 4) = h1;
    *(uint32_t*)(dlo)     = l0;
    *(uint32_t*)(dlo + 4) = l1;
}

// ---------------------------------------------------------------------------
// Fused K1+K2, barrier-free edge path, 3 CTAs/SM for latency hiding:
//   u % 11 == 10 -> node tile (128 nodes, block-wide): g_Q = xg @ Wn^T
//   otherwise    -> edge tile (128 edges): bf16-split mma.sync GEMM
//       N cols 0..63   -> out = elu(E @ W_e^T + b_e)
//       N cols 64..127 -> g_P = E @ W_edge[:, :64]^T
// ---------------------------------------------------------------------------
#define ASTRIDE 144
#define SM_BHI  0
#define SM_BLO  18432
#define SM_BIAS 36864
#define SM_NW   37120
#define SM_XS   (SM_NW + 10752)
#define SM_TOT  (SM_XS + 22176)   // 70048 B -> 3 CTAs/SM fits in 228 KB

__global__ __launch_bounds__(256, 3) void fused_gemm_kernel(
    const float* __restrict__ E,
    const float* __restrict__ W_edge,
    const float* __restrict__ W_e,
    const float* __restrict__ b_e,
    const float* __restrict__ x,
    const float* __restrict__ gs,
    float* __restrict__ out,
    int NE, int NN) {
    extern __shared__ char sm[];
    uint32_t smb = smem_u32(sm);
    float* Wn = (float*)(sm + SM_NW);
    float* Xs = (float*)(sm + SM_XS);
    int tid  = threadIdx.x;
    int wid  = tid >> 5;
    int lane = tid & 31;

    if (tid < 64) *(float*)(sm + SM_BIAS + tid * 4) = b_e[tid];

    // Edge weights (rows: 0..63 = W_e, 64..127 = W_edge[:, :64]) -> bf16 hi/lo
    for (int s = tid; s < 128 * 16; s += 256) {
        int o = s >> 4, q = s & 15;
        float4 v;
        if (o < 64) {
            v = *(const float4*)&W_e[o * 64 + q * 4];
        } else {
            const float* wr = &W_edge[(o - 64) * 106 + q * 4];
            v = make_float4(wr[0], wr[1], wr[2], wr[3]);
        }
        split_store(sm + SM_BHI + o * ASTRIDE + q * 8,
                    sm + SM_BLO + o * ASTRIDE + q * 8, v);
    }
    // Node weights fp32: Wn[k][o] = W_edge[o][64+k]
    for (int s = tid; s < 64 * 42; s += 256) {
        int o = s / 42, i = s % 42;
        Wn[i * 64 + o] = W_edge[o * 106 + 64 + i];
    }
    __syncthreads();   // weights visible to all warps

    int brow = lane & 7;
    int bk   = (lane >> 3) * 8;
    uint32_t boff = (uint32_t)(brow * ASTRIDE + bk * 2);
    int g  = lane >> 2;
    int tq = lane & 3;
    int cb = tq * 2;

    int ntiles_e = (NE + 127) >> 7;
    int ntiles_n = (NN + 127) >> 7;
    int nk = ntiles_n > (ntiles_e + 9) / 10 ? ntiles_n : (ntiles_e + 9) / 10;
    long long umax = 11LL * nk + 11;

    for (long long u = blockIdx.x; u < umax; u += gridDim.x) {
        int k11 = (int)(u / 11), r11 = (int)(u % 11);

        if (r11 == 10) {
            // ---------------- node tile (block-wide, synced) ----------------
            int tn = k11;
            if (tn >= ntiles_n) continue;
            int n0 = tn << 7;
            __syncthreads();   // prior node tile's Xs readers done
            for (int s = tid; s < 128 * 37; s += 256) {
                int nl = s / 37, i = s % 37;
                float v = (n0 + nl < NN) ? x[(size_t)n0 * 37 + s] : 0.f;
                Xs[i * 132 + nl] = v;
            }
            for (int s = tid; s < 128 * 5; s += 256) {
                int nl = s / 5, j = s % 5;
                float v = (n0 + nl < NN) ? gs[(size_t)n0 * 5 + s] : 0.f;
                Xs[(37 + j) * 132 + nl] = v;
            }
            __syncthreads();

            int tr = tid >> 3, tc = tid & 7;
            float acc[4][8];
#pragma unroll
            for (int r = 0; r < 4; r++)
#pragma unroll
                for (int c = 0; c < 8; c++) acc[r][c] = 0.f;

#pragma unroll 6
            for (int k = 0; k < 42; k++) {
                float a[4], w[8];
                *(float4*)a       = *(const float4*)&Xs[k * 132 + tr * 4];
                *(float4*)w       = *(const float4*)&Wn[k * 64 + tc * 8];
                *(float4*)(w + 4) = *(const float4*)&Wn[k * 64 + tc * 8 + 4];
#pragma unroll
                for (int r = 0; r < 4; r++)
#pragma unroll
                    for (int c = 0; c < 8; c++)
                        acc[r][c] = fmaf(a[r], w[c], acc[r][c]);
            }
#pragma unroll
            for (int r = 0; r < 4; r++) {
                int n = n0 + tr * 4 + r;
                if (n < NN) {
                    *(float4*)&g_Q[(size_t)n * 64 + tc * 8]     = *(float4*)&acc[r][0];
                    *(float4*)&g_Q[(size_t)n * 64 + tc * 8 + 4] = *(float4*)&acc[r][4];
                }
            }
        } else {
            // ---------------- edge tile (per-warp, barrier-free) ------------
            int te = k11 * 10 + r11;
            if (te >= ntiles_e) continue;
            int row0 = te << 7;

            // Build A fragments directly from global: warp owns 16 rows.
            int r0 = row0 + wid * 16 + g;
            int r1 = r0 + 8;
            uint32_t Ah[4][4], Al[4][4];
            const float2 z2 = make_float2(0.f, 0.f);
#pragma unroll
            for (int k = 0; k < 4; k++) {
                int c0 = k * 16 + cb;
                float2 v00 = z2, v01 = z2, v10 = z2, v11 = z2;
                if (r0 < NE) {
                    v00 = __ldg((const float2*)&E[(size_t)r0 * 64 + c0]);
                    v01 = __ldg((const float2*)&E[(size_t)r0 * 64 + c0 + 8]);
                }
                if (r1 < NE) {
                    v10 = __ldg((const float2*)&E[(size_t)r1 * 64 + c0]);
                    v11 = __ldg((const float2*)&E[(size_t)r1 * 64 + c0 + 8]);
                }
                Ah[k][0] = pack_bf(v00.x, v00.y);
                Ah[k][1] = pack_bf(v10.x, v10.y);
                Ah[k][2] = pack_bf(v01.x, v01.y);
                Ah[k][3] = pack_bf(v11.x, v11.y);
                Al[k][0] = resid_bf(v00.x, v00.y, Ah[k][0]);
                Al[k][1] = resid_bf(v10.x, v10.y, Ah[k][1]);
                Al[k][2] = resid_bf(v01.x, v01.y, Ah[k][2]);
                Al[k][3] = resid_bf(v11.x, v11.y, Ah[k][3]);
            }

#pragma unroll 2
            for (int j = 0; j < 16; j++) {
                uint32_t nb = (uint32_t)(j * 8 * ASTRIDE) + boff;
                uint32_t Bh[8], Bl[8];
                ldm_x4(Bh,     smb + SM_BHI + nb);
                ldm_x4(Bh + 4, smb + SM_BHI + nb + 64);
                ldm_x4(Bl,     smb + SM_BLO + nb);
                ldm_x4(Bl + 4, smb + SM_BLO + nb + 64);

                float acc[4] = {0.f, 0.f, 0.f, 0.f};
#pragma unroll
                for (int k = 0; k < 4; k++) {
                    mma_bf16(acc, Ah[k], Bh[k * 2], Bh[k * 2 + 1]);
                    mma_bf16(acc, Al[k], Bh[k * 2], Bh[k * 2 + 1]);
                    mma_bf16(acc, Ah[k], Bl[k * 2], Bl[k * 2 + 1]);
                }

                int ra = row0 + wid * 16 + g;
                int rb = ra + 8;
                int c  = j * 8 + tq * 2;
                if (j < 8) {
                    float2 bb = *(float2*)(sm + SM_BIAS + c * 4);
                    if (ra < NE) {
                        float2 v = make_float2(eluf(acc[0] + bb.x), eluf(acc[1] + bb.y));
                        *(float2*)&out[(size_t)ra * 64 + c] = v;
                    }
                    if (rb < NE) {
                        float2 v = make_float2(eluf(acc[2] + bb.x), eluf(acc[3] + bb.y));
                        *(float2*)&out[(size_t)rb * 64 + c] = v;
                    }
                } else {
                    int cp = c - 64;
                    if (ra < NE)
                        *(float2*)&g_P[(size_t)ra * 64 + cp] = make_float2(acc[0], acc[1]);
                    if (rb < NE)
                        *(float2*)&g_P[(size_t)rb * 64 + cp] = make_float2(acc[2], acc[3]);
                }
            }
        }
    }
}

// ---------------------------------------------------------------------------
// K3: per pair k:  h = elu(P[e1] + Q[a0] + b_edge);  out[e0] += h
// (round-8/12 exact form — empirical K3 floor: ~242us @ 74% DRAM)
// ---------------------------------------------------------------------------
__global__ void pair_scatter_kernel(const float* __restrict__ b_edge,
                                    const int* __restrict__ aidx,
                                    const int* __restrict__ eidx,
                                    float* __restrict__ out,
                                    int NP) {
    __shared__ float bs[64];
    int tid = threadIdx.x;
    if (tid < 64) bs[tid] = b_edge[tid];
    __syncthreads();

    int pl = tid >> 4;
    int q  = tid & 15;
    long long k = (long long)blockIdx.x * 16 + pl;
    if (k >= NP) return;

    int e0 = eidx[k];
    int e1 = eidx[(size_t)NP + k];
    int a0 = aidx[k];

    float4 p  = __ldg((const float4*)&g_P[(size_t)e1 * 64 + q * 4]);
    float4 qv = __ldg((const float4*)&g_Q[(size_t)a0 * 64 + q * 4]);

    float h0 = eluf(p.x + qv.x + bs[q * 4 + 0]);
    float h1 = eluf(p.y + qv.y + bs[q * 4 + 1]);
    float h2 = eluf(p.z + qv.z + bs[q * 4 + 2]);
    float h3 = eluf(p.w + qv.w + bs[q * 4 + 3]);

    float* addr = out + (size_t)e0 * 64 + q * 4;
    asm volatile("red.global.add.v4.f32 [%0], {%1,%2,%3,%4};"
                 :: "l"(addr), "f"(h0), "f"(h1), "f"(h2), "f"(h3)
                 : "memory");
}

// ---------------------------------------------------------------------------
extern "C" void kernel_launch(void* const* d_in, const int* in_sizes, int n_in,
                              void* d_out, int out_size) {
    const float* x      = (const float*)d_in[0];
    const float* gs     = (const float*)d_in[1];
    const float* E      = (const float*)d_in[2];
    const float* W_edge = (const float*)d_in[3];
    const float* b_edge = (const float*)d_in[4];
    const float* W_e    = (const float*)d_in[5];
    const float* b_e    = (const float*)d_in[6];
    const int*   aidx   = (const int*)d_in[7];
    const int*   eidx   = (const int*)d_in[8];
    float* out = (float*)d_out;

    int NN = in_sizes[0] / 37;
    int NE = in_sizes[2] / 64;
    int NP = in_sizes[7] / 2;
    if (NN > NN_MAX) NN = NN_MAX;
    if (NE > NE_MAX) NE = NE_MAX;

    cudaFuncSetAttribute(fused_gemm_kernel,
                         cudaFuncAttributeMaxDynamicSharedMemorySize, SM_TOT);
    fused_gemm_kernel<<<444, 256, SM_TOT>>>(E, W_edge, W_e, b_e, x, gs, out, NE, NN);

    int t3 = (NP + 15) / 16;
    pair_scatter_kernel<<<t3, 256>>>(b_edge, aidx, eidx, out, NP);
}

// round 15
// speedup vs baseline: 1.0785x; 1.0319x over previous
#include <cuda_runtime.h>
#include <cuda_bf16.h>
#include <cuda_fp16.h>
#include <cstdint>

// Fixed problem maxima (from reference): 1M edges, 100K nodes, 2M pairs.
#define NE_MAX 1000000
#define NN_MAX 100000

__device__ __half g_P[(size_t)NE_MAX * 64]; // fp16: edge_attr @ W_edge[:, :64]^T
__device__ float  g_Q[(size_t)NN_MAX * 64]; // fp32: [x|gs] @ W_edge[:, 64:]^T

__device__ __forceinline__ float eluf(float x) {
    return x > 0.f ? x : (__expf(x) - 1.f);
}
__device__ __forceinline__ uint32_t smem_u32(const void* p) {
    uint32_t a;
    asm("{ .reg .u64 t; cvta.to.shared.u64 t, %1; cvt.u32.u64 %0, t; }" : "=r"(a) : "l"(p));
    return a;
}
// pack two floats to bf16x2 (first arg -> low 16 bits)
__device__ __forceinline__ uint32_t pack_bf(float lo, float hi) {
    uint32_t r; asm("cvt.rn.bf16x2.f32 %0, %1, %2;" : "=r"(r) : "f"(hi), "f"(lo)); return r;
}
// residual (lo-part) of a float2 vs its packed bf16 hi
__device__ __forceinline__ uint32_t resid_bf(float a, float b, uint32_t h) {
    return pack_bf(a - __uint_as_float(h << 16), b - __uint_as_float(h & 0xFFFF0000u));
}
__device__ __forceinline__ void ldm_x4(uint32_t* r, uint32_t addr) {
    asm volatile("ldmatrix.sync.aligned.m8n8.x4.shared.b16 {%0,%1,%2,%3}, [%4];"
                 : "=r"(r[0]), "=r"(r[1]), "=r"(r[2]), "=r"(r[3]) : "r"(addr));
}
__device__ __forceinline__ void mma_bf16(float* d, const uint32_t* a, uint32_t b0, uint32_t b1) {
    asm volatile(
        "mma.sync.aligned.m16n8k16.row.col.f32.bf16.bf16.f32 "
        "{%0,%1,%2,%3}, {%4,%5,%6,%7}, {%8,%9}, {%0,%1,%2,%3};"
        : "+f"(d[0]), "+f"(d[1]), "+f"(d[2]), "+f"(d[3])
        : "r"(a[0]), "r"(a[1]), "r"(a[2]), "r"(a[3]), "r"(b0), "r"(b1));
}
__device__ __forceinline__ void split_store(char* dhi, char* dlo, float4 v) {
    uint32_t h0 = pack_bf(v.x, v.y);
    uint32_t l0 = resid_bf(v.x, v.y, h0);
    uint32_t h1 = pack_bf(v.z, v.w);
    uint32_t l1 = resid_bf(v.z, v.w, h1);
    *(uint32_t*)(dhi)     = h0;
    *(uint32_t*)(dhi + 4) = h1;
    *(uint32_t*)(dlo)     = l0;
    *(uint32_t*)(dlo + 4) = l1;
}

// ---------------------------------------------------------------------------
// Fused K1+K2, barrier-free edge path, 3 CTAs/SM:
//   u % 11 == 10 -> node tile (128 nodes, block-wide): g_Q = xg @ Wn^T
//   otherwise    -> edge tile (128 edges): bf16-split mma.sync GEMM
//       N cols 0..63   -> out = elu(E @ W_e^T + b_e)        (fp32)
//       N cols 64..127 -> g_P = E @ W_edge[:, :64]^T        (stored fp16)
// ---------------------------------------------------------------------------
#define ASTRIDE 144
#define SM_BHI  0
#define SM_BLO  18432
#define SM_BIAS 36864
#define SM_NW   37120
#define SM_XS   (SM_NW + 10752)
#define SM_TOT  (SM_XS + 22176)   // 70048 B -> 3 CTAs/SM

__global__ __launch_bounds__(256, 3) void fused_gemm_kernel(
    const float* __restrict__ E,
    const float* __restrict__ W_edge,
    const float* __restrict__ W_e,
    const float* __restrict__ b_e,
    const float* __restrict__ x,
    const float* __restrict__ gs,
    float* __restrict__ out,
    int NE, int NN) {
    extern __shared__ char sm[];
    uint32_t smb = smem_u32(sm);
    float* Wn = (float*)(sm + SM_NW);
    float* Xs = (float*)(sm + SM_XS);
    int tid  = threadIdx.x;
    int wid  = tid >> 5;
    int lane = tid & 31;

    if (tid < 64) *(float*)(sm + SM_BIAS + tid * 4) = b_e[tid];

    // Edge weights (rows: 0..63 = W_e, 64..127 = W_edge[:, :64]) -> bf16 hi/lo
    for (int s = tid; s < 128 * 16; s += 256) {
        int o = s >> 4, q = s & 15;
        float4 v;
        if (o < 64) {
            v = *(const float4*)&W_e[o * 64 + q * 4];
        } else {
            const float* wr = &W_edge[(o - 64) * 106 + q * 4];
            v = make_float4(wr[0], wr[1], wr[2], wr[3]);
        }
        split_store(sm + SM_BHI + o * ASTRIDE + q * 8,
                    sm + SM_BLO + o * ASTRIDE + q * 8, v);
    }
    // Node weights fp32: Wn[k][o] = W_edge[o][64+k]
    for (int s = tid; s < 64 * 42; s += 256) {
        int o = s / 42, i = s % 42;
        Wn[i * 64 + o] = W_edge[o * 106 + 64 + i];
    }
    __syncthreads();   // weights visible to all warps

    int brow = lane & 7;
    int bk   = (lane >> 3) * 8;
    uint32_t boff = (uint32_t)(brow * ASTRIDE + bk * 2);
    int g  = lane >> 2;
    int tq = lane & 3;
    int cb = tq * 2;

    int ntiles_e = (NE + 127) >> 7;
    int ntiles_n = (NN + 127) >> 7;
    int nk = ntiles_n > (ntiles_e + 9) / 10 ? ntiles_n : (ntiles_e + 9) / 10;
    long long umax = 11LL * nk + 11;

    for (long long u = blockIdx.x; u < umax; u += gridDim.x) {
        int k11 = (int)(u / 11), r11 = (int)(u % 11);

        if (r11 == 10) {
            // ---------------- node tile (block-wide, synced) ----------------
            int tn = k11;
            if (tn >= ntiles_n) continue;
            int n0 = tn << 7;
            __syncthreads();   // prior node tile's Xs readers done
            for (int s = tid; s < 128 * 37; s += 256) {
                int nl = s / 37, i = s % 37;
                float v = (n0 + nl < NN) ? x[(size_t)n0 * 37 + s] : 0.f;
                Xs[i * 132 + nl] = v;
            }
            for (int s = tid; s < 128 * 5; s += 256) {
                int nl = s / 5, j = s % 5;
                float v = (n0 + nl < NN) ? gs[(size_t)n0 * 5 + s] : 0.f;
                Xs[(37 + j) * 132 + nl] = v;
            }
            __syncthreads();

            int tr = tid >> 3, tc = tid & 7;
            float acc[4][8];
#pragma unroll
            for (int r = 0; r < 4; r++)
#pragma unroll
                for (int c = 0; c < 8; c++) acc[r][c] = 0.f;

#pragma unroll 6
            for (int k = 0; k < 42; k++) {
                float a[4], w[8];
                *(float4*)a       = *(const float4*)&Xs[k * 132 + tr * 4];
                *(float4*)w       = *(const float4*)&Wn[k * 64 + tc * 8];
                *(float4*)(w + 4) = *(const float4*)&Wn[k * 64 + tc * 8 + 4];
#pragma unroll
                for (int r = 0; r < 4; r++)
#pragma unroll
                    for (int c = 0; c < 8; c++)
                        acc[r][c] = fmaf(a[r], w[c], acc[r][c]);
            }
#pragma unroll
            for (int r = 0; r < 4; r++) {
                int n = n0 + tr * 4 + r;
                if (n < NN) {
                    *(float4*)&g_Q[(size_t)n * 64 + tc * 8]     = *(float4*)&acc[r][0];
                    *(float4*)&g_Q[(size_t)n * 64 + tc * 8 + 4] = *(float4*)&acc[r][4];
                }
            }
        } else {
            // ---------------- edge tile (per-warp, barrier-free) ------------
            int te = k11 * 10 + r11;
            if (te >= ntiles_e) continue;
            int row0 = te << 7;

            // Build A fragments directly from global: warp owns 16 rows.
            int r0 = row0 + wid * 16 + g;
            int r1 = r0 + 8;
            uint32_t Ah[4][4], Al[4][4];
            const float2 z2 = make_float2(0.f, 0.f);
#pragma unroll
            for (int k = 0; k < 4; k++) {
                int c0 = k * 16 + cb;
                float2 v00 = z2, v01 = z2, v10 = z2, v11 = z2;
                if (r0 < NE) {
                    v00 = __ldg((const float2*)&E[(size_t)r0 * 64 + c0]);
                    v01 = __ldg((const float2*)&E[(size_t)r0 * 64 + c0 + 8]);
                }
                if (r1 < NE) {
                    v10 = __ldg((const float2*)&E[(size_t)r1 * 64 + c0]);
                    v11 = __ldg((const float2*)&E[(size_t)r1 * 64 + c0 + 8]);
                }
                Ah[k][0] = pack_bf(v00.x, v00.y);
                Ah[k][1] = pack_bf(v10.x, v10.y);
                Ah[k][2] = pack_bf(v01.x, v01.y);
                Ah[k][3] = pack_bf(v11.x, v11.y);
                Al[k][0] = resid_bf(v00.x, v00.y, Ah[k][0]);
                Al[k][1] = resid_bf(v10.x, v10.y, Ah[k][1]);
                Al[k][2] = resid_bf(v01.x, v01.y, Ah[k][2]);
                Al[k][3] = resid_bf(v11.x, v11.y, Ah[k][3]);
            }

#pragma unroll 2
            for (int j = 0; j < 16; j++) {
                uint32_t nb = (uint32_t)(j * 8 * ASTRIDE) + boff;
                uint32_t Bh[8], Bl[8];
                ldm_x4(Bh,     smb + SM_BHI + nb);
                ldm_x4(Bh + 4, smb + SM_BHI + nb + 64);
                ldm_x4(Bl,     smb + SM_BLO + nb);
                ldm_x4(Bl + 4, smb + SM_BLO + nb + 64);

                float acc[4] = {0.f, 0.f, 0.f, 0.f};
#pragma unroll
                for (int k = 0; k < 4; k++) {
                    mma_bf16(acc, Ah[k], Bh[k * 2], Bh[k * 2 + 1]);
                    mma_bf16(acc, Al[k], Bh[k * 2], Bh[k * 2 + 1]);
                    mma_bf16(acc, Ah[k], Bl[k * 2], Bl[k * 2 + 1]);
                }

                int ra = row0 + wid * 16 + g;
                int rb = ra + 8;
                int c  = j * 8 + tq * 2;
                if (j < 8) {
                    float2 bb = *(float2*)(sm + SM_BIAS + c * 4);
                    if (ra < NE) {
                        float2 v = make_float2(eluf(acc[0] + bb.x), eluf(acc[1] + bb.y));
                        *(float2*)&out[(size_t)ra * 64 + c] = v;
                    }
                    if (rb < NE) {
                        float2 v = make_float2(eluf(acc[2] + bb.x), eluf(acc[3] + bb.y));
                        *(float2*)&out[(size_t)rb * 64 + c] = v;
                    }
                } else {
                    int cp = c - 64;
                    if (ra < NE)
                        *(__half2*)&g_P[(size_t)ra * 64 + cp] =
                            __floats2half2_rn(acc[0], acc[1]);
                    if (rb < NE)
                        *(__half2*)&g_P[(size_t)rb * 64 + cp] =
                            __floats2half2_rn(acc[2], acc[3]);
                }
            }
        }
    }
}

// ---------------------------------------------------------------------------
// K3: per pair k:  h = elu(P[e1] + Q[a0] + b_edge);  out[e0] += h
// P gathered as fp16 (128 B/row = one cache line), Q fp32 (L2-resident).
// ---------------------------------------------------------------------------
__global__ void pair_scatter_kernel(const float* __restrict__ b_edge,
                                    const int* __restrict__ aidx,
                                    const int* __restrict__ eidx,
                                    float* __restrict__ out,
                                    int NP) {
    __shared__ float bs[64];
    int tid = threadIdx.x;
    if (tid < 64) bs[tid] = b_edge[tid];
    __syncthreads();

    int pl = tid >> 4;
    int q  = tid & 15;
    long long k = (long long)blockIdx.x * 16 + pl;
    if (k >= NP) return;

    int e0 = eidx[k];
    int e1 = eidx[(size_t)NP + k];
    int a0 = aidx[k];

    // 4 halves (8 B) of P row + 4 floats (16 B) of Q row
    uint2 pr = __ldg((const uint2*)&g_P[(size_t)e1 * 64 + q * 4]);
    float2 p01 = __half22float2(*(__half2*)&pr.x);
    float2 p23 = __half22float2(*(__half2*)&pr.y);
    float4 qv = __ldg((const float4*)&g_Q[(size_t)a0 * 64 + q * 4]);

    float h0 = eluf(p01.x + qv.x + bs[q * 4 + 0]);
    float h1 = eluf(p01.y + qv.y + bs[q * 4 + 1]);
    float h2 = eluf(p23.x + qv.z + bs[q * 4 + 2]);
    float h3 = eluf(p23.y + qv.w + bs[q * 4 + 3]);

    float* addr = out + (size_t)e0 * 64 + q * 4;
    asm volatile("red.global.add.v4.f32 [%0], {%1,%2,%3,%4};"
                 :: "l"(addr), "f"(h0), "f"(h1), "f"(h2), "f"(h3)
                 : "memory");
}

// ---------------------------------------------------------------------------
extern "C" void kernel_launch(void* const* d_in, const int* in_sizes, int n_in,
                              void* d_out, int out_size) {
    const float* x      = (const float*)d_in[0];
    const float* gs     = (const float*)d_in[1];
    const float* E      = (const float*)d_in[2];
    const float* W_edge = (const float*)d_in[3];
    const float* b_edge = (const float*)d_in[4];
    const float* W_e    = (const float*)d_in[5];
    const float* b_e    = (const float*)d_in[6];
    const int*   aidx   = (const int*)d_in[7];
    const int*   eidx   = (const int*)d_in[8];
    float* out = (float*)d_out;

    int NN = in_sizes[0] / 37;
    int NE = in_sizes[2] / 64;
    int NP = in_sizes[7] / 2;
    if (NN > NN_MAX) NN = NN_MAX;
    if (NE > NE_MAX) NE = NE_MAX;

    cudaFuncSetAttribute(fused_gemm_kernel,
                         cudaFuncAttributeMaxDynamicSharedMemorySize, SM_TOT);
    fused_gemm_kernel<<<444, 256, SM_TOT>>>(E, W_edge, W_e, b_e, x, gs, out, NE, NN);

    int t3 = (NP + 15) / 16;
    pair_scatter_kernel<<<t3, 256>>>(b_edge, aidx, eidx, out, NP);
}

// round 16
// speedup vs baseline: 1.1110x; 1.0301x over previous
#include <cuda_runtime.h>
#include <cuda_bf16.h>
#include <cuda_fp16.h>
#include <cstdint>

// Fixed problem maxima (from reference): 1M edges, 100K nodes, 2M pairs.
#define NE_MAX 1000000
#define NN_MAX 100000

__device__ __half g_P[(size_t)NE_MAX * 64]; // fp16: edge_attr @ W_edge[:, :64]^T
__device__ __half g_Q[(size_t)NN_MAX * 64]; // fp16: [x|gs] @ W_edge[:, 64:]^T + b_edge

__device__ __forceinline__ float eluf(float x) {
    return x > 0.f ? x : (__expf(x) - 1.f);
}
__device__ __forceinline__ uint32_t smem_u32(const void* p) {
    uint32_t a;
    asm("{ .reg .u64 t; cvta.to.shared.u64 t, %1; cvt.u32.u64 %0, t; }" : "=r"(a) : "l"(p));
    return a;
}
// pack two floats to bf16x2 (first arg -> low 16 bits)
__device__ __forceinline__ uint32_t pack_bf(float lo, float hi) {
    uint32_t r; asm("cvt.rn.bf16x2.f32 %0, %1, %2;" : "=r"(r) : "f"(hi), "f"(lo)); return r;
}
// residual (lo-part) of a float2 vs its packed bf16 hi
__device__ __forceinline__ uint32_t resid_bf(float a, float b, uint32_t h) {
    return pack_bf(a - __uint_as_float(h << 16), b - __uint_as_float(h & 0xFFFF0000u));
}
__device__ __forceinline__ void ldm_x4(uint32_t* r, uint32_t addr) {
    asm volatile("ldmatrix.sync.aligned.m8n8.x4.shared.b16 {%0,%1,%2,%3}, [%4];"
                 : "=r"(r[0]), "=r"(r[1]), "=r"(r[2]), "=r"(r[3]) : "r"(addr));
}
__device__ __forceinline__ void mma_bf16(float* d, const uint32_t* a, uint32_t b0, uint32_t b1) {
    asm volatile(
        "mma.sync.aligned.m16n8k16.row.col.f32.bf16.bf16.f32 "
        "{%0,%1,%2,%3}, {%4,%5,%6,%7}, {%8,%9}, {%0,%1,%2,%3};"
        : "+f"(d[0]), "+f"(d[1]), "+f"(d[2]), "+f"(d[3])
        : "r"(a[0]), "r"(a[1]), "r"(a[2]), "r"(a[3]), "r"(b0), "r"(b1));
}
__device__ __forceinline__ void split_store(char* dhi, char* dlo, float4 v) {
    uint32_t h0 = pack_bf(v.x, v.y);
    uint32_t l0 = resid_bf(v.x, v.y, h0);
    uint32_t h1 = pack_bf(v.z, v.w);
    uint32_t l1 = resid_bf(v.z, v.w, h1);
    *(uint32_t*)(dhi)     = h0;
    *(uint32_t*)(dhi + 4) = h1;
    *(uint32_t*)(dlo)     = l0;
    *(uint32_t*)(dlo + 4) = l1;
}

// ---------------------------------------------------------------------------
// Fused K1+K2, barrier-free edge path, 3 CTAs/SM:
//   u % 11 == 10 -> node tile (128 nodes, block-wide):
//                   g_Q = fp16(xg @ Wn^T + b_edge)
//   otherwise    -> edge tile (128 edges): bf16-split mma.sync GEMM
//       N cols 0..63   -> out = elu(E @ W_e^T + b_e)        (fp32)
//       N cols 64..127 -> g_P = E @ W_edge[:, :64]^T        (stored fp16)
// ---------------------------------------------------------------------------
#define ASTRIDE 144
#define SM_BHI  0
#define SM_BLO  18432
#define SM_BIAS 36864              // b_e (64 floats)
#define SM_BEDGE 37120             // b_edge (64 floats)
#define SM_NW   37376              // node weights: 42*64*4 = 10752 B
#define SM_XS   (SM_NW + 10752)
#define SM_TOT  (SM_XS + 22176)    // 70304 B -> 3 CTAs/SM

__global__ __launch_bounds__(256, 3) void fused_gemm_kernel(
    const float* __restrict__ E,
    const float* __restrict__ W_edge,
    const float* __restrict__ W_e,
    const float* __restrict__ b_e,
    const float* __restrict__ b_edge,
    const float* __restrict__ x,
    const float* __restrict__ gs,
    float* __restrict__ out,
    int NE, int NN) {
    extern __shared__ char sm[];
    uint32_t smb = smem_u32(sm);
    float* Wn = (float*)(sm + SM_NW);
    float* Xs = (float*)(sm + SM_XS);
    int tid  = threadIdx.x;
    int wid  = tid >> 5;
    int lane = tid & 31;

    if (tid < 64)  *(float*)(sm + SM_BIAS + tid * 4)  = b_e[tid];
    if (tid >= 64 && tid < 128)
        *(float*)(sm + SM_BEDGE + (tid - 64) * 4) = b_edge[tid - 64];

    // Edge weights (rows: 0..63 = W_e, 64..127 = W_edge[:, :64]) -> bf16 hi/lo
    for (int s = tid; s < 128 * 16; s += 256) {
        int o = s >> 4, q = s & 15;
        float4 v;
        if (o < 64) {
            v = *(const float4*)&W_e[o * 64 + q * 4];
        } else {
            const float* wr = &W_edge[(o - 64) * 106 + q * 4];
            v = make_float4(wr[0], wr[1], wr[2], wr[3]);
        }
        split_store(sm + SM_BHI + o * ASTRIDE + q * 8,
                    sm + SM_BLO + o * ASTRIDE + q * 8, v);
    }
    // Node weights fp32: Wn[k][o] = W_edge[o][64+k]
    for (int s = tid; s < 64 * 42; s += 256) {
        int o = s / 42, i = s % 42;
        Wn[i * 64 + o] = W_edge[o * 106 + 64 + i];
    }
    __syncthreads();   // weights + biases visible to all warps

    int brow = lane & 7;
    int bk   = (lane >> 3) * 8;
    uint32_t boff = (uint32_t)(brow * ASTRIDE + bk * 2);
    int g  = lane >> 2;
    int tq = lane & 3;
    int cb = tq * 2;

    int ntiles_e = (NE + 127) >> 7;
    int ntiles_n = (NN + 127) >> 7;
    int nk = ntiles_n > (ntiles_e + 9) / 10 ? ntiles_n : (ntiles_e + 9) / 10;
    long long umax = 11LL * nk + 11;

    for (long long u = blockIdx.x; u < umax; u += gridDim.x) {
        int k11 = (int)(u / 11), r11 = (int)(u % 11);

        if (r11 == 10) {
            // ---------------- node tile (block-wide, synced) ----------------
            int tn = k11;
            if (tn >= ntiles_n) continue;
            int n0 = tn << 7;
            __syncthreads();   // prior node tile's Xs readers done
            for (int s = tid; s < 128 * 37; s += 256) {
                int nl = s / 37, i = s % 37;
                float v = (n0 + nl < NN) ? x[(size_t)n0 * 37 + s] : 0.f;
                Xs[i * 132 + nl] = v;
            }
            for (int s = tid; s < 128 * 5; s += 256) {
                int nl = s / 5, j = s % 5;
                float v = (n0 + nl < NN) ? gs[(size_t)n0 * 5 + s] : 0.f;
                Xs[(37 + j) * 132 + nl] = v;
            }
            __syncthreads();

            int tr = tid >> 3, tc = tid & 7;
            float acc[4][8];
            // init accumulators with folded b_edge bias
            float binit[8];
            *(float4*)binit       = *(float4*)(sm + SM_BEDGE + tc * 32);
            *(float4*)(binit + 4) = *(float4*)(sm + SM_BEDGE + tc * 32 + 16);
#pragma unroll
            for (int r = 0; r < 4; r++)
#pragma unroll
                for (int c = 0; c < 8; c++) acc[r][c] = binit[c];

#pragma unroll 6
            for (int k = 0; k < 42; k++) {
                float a[4], w[8];
                *(float4*)a       = *(const float4*)&Xs[k * 132 + tr * 4];
                *(float4*)w       = *(const float4*)&Wn[k * 64 + tc * 8];
                *(float4*)(w + 4) = *(const float4*)&Wn[k * 64 + tc * 8 + 4];
#pragma unroll
                for (int r = 0; r < 4; r++)
#pragma unroll
                    for (int c = 0; c < 8; c++)
                        acc[r][c] = fmaf(a[r], w[c], acc[r][c]);
            }
#pragma unroll
            for (int r = 0; r < 4; r++) {
                int n = n0 + tr * 4 + r;
                if (n < NN) {
                    __half2 h0 = __floats2half2_rn(acc[r][0], acc[r][1]);
                    __half2 h1 = __floats2half2_rn(acc[r][2], acc[r][3]);
                    __half2 h2 = __floats2half2_rn(acc[r][4], acc[r][5]);
                    __half2 h3 = __floats2half2_rn(acc[r][6], acc[r][7]);
                    uint4 pk = make_uint4(*(uint32_t*)&h0, *(uint32_t*)&h1,
                                          *(uint32_t*)&h2, *(uint32_t*)&h3);
                    *(uint4*)&g_Q[(size_t)n * 64 + tc * 8] = pk;
                }
            }
        } else {
            // ---------------- edge tile (per-warp, barrier-free) ------------
            int te = k11 * 10 + r11;
            if (te >= ntiles_e) continue;
            int row0 = te << 7;

            // Build A fragments directly from global: warp owns 16 rows.
            int r0 = row0 + wid * 16 + g;
            int r1 = r0 + 8;
            uint32_t Ah[4][4], Al[4][4];
            const float2 z2 = make_float2(0.f, 0.f);
#pragma unroll
            for (int k = 0; k < 4; k++) {
                int c0 = k * 16 + cb;
                float2 v00 = z2, v01 = z2, v10 = z2, v11 = z2;
                if (r0 < NE) {
                    v00 = __ldg((const float2*)&E[(size_t)r0 * 64 + c0]);
                    v01 = __ldg((const float2*)&E[(size_t)r0 * 64 + c0 + 8]);
                }
                if (r1 < NE) {
                    v10 = __ldg((const float2*)&E[(size_t)r1 * 64 + c0]);
                    v11 = __ldg((const float2*)&E[(size_t)r1 * 64 + c0 + 8]);
                }
                Ah[k][0] = pack_bf(v00.x, v00.y);
                Ah[k][1] = pack_bf(v10.x, v10.y);
                Ah[k][2] = pack_bf(v01.x, v01.y);
                Ah[k][3] = pack_bf(v11.x, v11.y);
                Al[k][0] = resid_bf(v00.x, v00.y, Ah[k][0]);
                Al[k][1] = resid_bf(v10.x, v10.y, Ah[k][1]);
                Al[k][2] = resid_bf(v01.x, v01.y, Ah[k][2]);
                Al[k][3] = resid_bf(v11.x, v11.y, Ah[k][3]);
            }

#pragma unroll 2
            for (int j = 0; j < 16; j++) {
                uint32_t nb = (uint32_t)(j * 8 * ASTRIDE) + boff;
                uint32_t Bh[8], Bl[8];
                ldm_x4(Bh,     smb + SM_BHI + nb);
                ldm_x4(Bh + 4, smb + SM_BHI + nb + 64);
                ldm_x4(Bl,     smb + SM_BLO + nb);
                ldm_x4(Bl + 4, smb + SM_BLO + nb + 64);

                float acc[4] = {0.f, 0.f, 0.f, 0.f};
#pragma unroll
                for (int k = 0; k < 4; k++) {
                    mma_bf16(acc, Ah[k], Bh[k * 2], Bh[k * 2 + 1]);
                    mma_bf16(acc, Al[k], Bh[k * 2], Bh[k * 2 + 1]);
                    mma_bf16(acc, Ah[k], Bl[k * 2], Bl[k * 2 + 1]);
                }

                int ra = row0 + wid * 16 + g;
                int rb = ra + 8;
                int c  = j * 8 + tq * 2;
                if (j < 8) {
                    float2 bb = *(float2*)(sm + SM_BIAS + c * 4);
                    if (ra < NE) {
                        float2 v = make_float2(eluf(acc[0] + bb.x), eluf(acc[1] + bb.y));
                        *(float2*)&out[(size_t)ra * 64 + c] = v;
                    }
                    if (rb < NE) {
                        float2 v = make_float2(eluf(acc[2] + bb.x), eluf(acc[3] + bb.y));
                        *(float2*)&out[(size_t)rb * 64 + c] = v;
                    }
                } else {
                    int cp = c - 64;
                    if (ra < NE)
                        *(__half2*)&g_P[(size_t)ra * 64 + cp] =
                            __floats2half2_rn(acc[0], acc[1]);
                    if (rb < NE)
                        *(__half2*)&g_P[(size_t)rb * 64 + cp] =
                            __floats2half2_rn(acc[2], acc[3]);
                }
            }
        }
    }
}

// ---------------------------------------------------------------------------
// K3: per pair k:  h = elu(P[e1] + Q'[a0]);  out[e0] += h
// P and Q' both fp16, one cache line per row; bias pre-folded into Q'.
// ---------------------------------------------------------------------------
__global__ void pair_scatter_kernel(const int* __restrict__ aidx,
                                    const int* __restrict__ eidx,
                                    float* __restrict__ out,
                                    int NP) {
    int tid = threadIdx.x;
    int pl = tid >> 4;
    int q  = tid & 15;
    long long k = (long long)blockIdx.x * 16 + pl;
    if (k >= NP) return;

    int e0 = eidx[k];
    int e1 = eidx[(size_t)NP + k];
    int a0 = aidx[k];

    uint2 pr = __ldg((const uint2*)&g_P[(size_t)e1 * 64 + q * 4]);
    uint2 qr = __ldg((const uint2*)&g_Q[(size_t)a0 * 64 + q * 4]);
    float2 p01 = __half22float2(*(__half2*)&pr.x);
    float2 p23 = __half22float2(*(__half2*)&pr.y);
    float2 q01 = __half22float2(*(__half2*)&qr.x);
    float2 q23 = __half22float2(*(__half2*)&qr.y);

    float h0 = eluf(p01.x + q01.x);
    float h1 = eluf(p01.y + q01.y);
    float h2 = eluf(p23.x + q23.x);
    float h3 = eluf(p23.y + q23.y);

    float* addr = out + (size_t)e0 * 64 + q * 4;
    asm volatile("red.global.add.v4.f32 [%0], {%1,%2,%3,%4};"
                 :: "l"(addr), "f"(h0), "f"(h1), "f"(h2), "f"(h3)
                 : "memory");
}

// ---------------------------------------------------------------------------
extern "C" void kernel_launch(void* const* d_in, const int* in_sizes, int n_in,
                              void* d_out, int out_size) {
    const float* x      = (const float*)d_in[0];
    const float* gs     = (const float*)d_in[1];
    const float* E      = (const float*)d_in[2];
    const float* W_edge = (const float*)d_in[3];
    const float* b_edge = (const float*)d_in[4];
    const float* W_e    = (const float*)d_in[5];
    const float* b_e    = (const float*)d_in[6];
    const int*   aidx   = (const int*)d_in[7];
    const int*   eidx   = (const int*)d_in[8];
    float* out = (float*)d_out;

    int NN = in_sizes[0] / 37;
    int NE = in_sizes[2] / 64;
    int NP = in_sizes[7] / 2;
    if (NN > NN_MAX) NN = NN_MAX;
    if (NE > NE_MAX) NE = NE_MAX;

    cudaFuncSetAttribute(fused_gemm_kernel,
                         cudaFuncAttributeMaxDynamicSharedMemorySize, SM_TOT);
    fused_gemm_kernel<<<444, 256, SM_TOT>>>(E, W_edge, W_e, b_e, b_edge,
                                            x, gs, out, NE, NN);

    int t3 = (NP + 15) / 16;
    pair_scatter_kernel<<<t3, 256>>>(aidx, eidx, out, NP);
}